// round 1
// baseline (speedup 1.0000x reference)
#include <cuda_runtime.h>

// Conv1dGroup: out[b,t,g,o] = sum_{f,k} x[b, t+k-1, g, f] * w[g,o,f,k] + bias[g,o]
// x: [B,T,G,F] f32, w: [G,O,F,K] f32, bias: [G,O] f32, out: [B,T,G,O] f32
// B=4, T=512, G=129, F=96, O=96, K=3

#define CB 4
#define CT 512
#define CG 129
#define CF 96
#define CO 96
#define CK 3

#define TILE_T 128
#define TT (TILE_T + 2)          // 130 x rows (halo of 1 on each side)
#define XST (CF + 1)             // 97: x smem row stride (conflict-free)
#define FK (CF * CK)             // 288
#define WST (FK + 1)             // 289: w smem row stride (conflict-free)

#define SMEM_FLOATS (CO * WST + TT * XST)   // 27744 + 12610 = 40354
#define SMEM_BYTES (SMEM_FLOATS * 4)        // 161416

__global__ __launch_bounds__(256, 1)
void conv1d_group_kernel(const float* __restrict__ x,
                         const float* __restrict__ w,
                         const float* __restrict__ bias,
                         float* __restrict__ out)
{
    extern __shared__ float sh[];
    float* w_sh = sh;                 // [CO][WST], logical [o][f*3+k]
    float* x_sh = sh + CO * WST;      // [TT][XST], row r = global t0-1+r

    const int g  = blockIdx.x;
    const int t0 = blockIdx.y * TILE_T;
    const int b  = blockIdx.z;
    const int tid = threadIdx.x;
    const int tx = tid & 15;          // o-group: o = tx*6 + j
    const int ty = tid >> 4;          // t lane: t_local = ty + i*16

    // ---- Stage weights for this group: [O][F*K] contiguous in gmem ----
    {
        const float4* wg = reinterpret_cast<const float4*>(w + (size_t)g * CO * FK);
        #pragma unroll 4
        for (int idx = tid; idx < CO * FK / 4; idx += 256) {
            int o = idx / (FK / 4);
            int c = idx - o * (FK / 4);
            float4 v = wg[idx];
            float* d = &w_sh[o * WST + c * 4];
            d[0] = v.x; d[1] = v.y; d[2] = v.z; d[3] = v.w;
        }
    }

    // ---- Stage x tile rows t0-1 .. t0+TILE_T (zero-pad out of range) ----
    {
        #pragma unroll 4
        for (int idx = tid; idx < TT * (CF / 4); idx += 256) {
            int r = idx / (CF / 4);
            int c = idx - r * (CF / 4);
            int t = t0 - 1 + r;
            float4 v = make_float4(0.f, 0.f, 0.f, 0.f);
            if (t >= 0 && t < CT) {
                v = reinterpret_cast<const float4*>(
                        x + ((size_t)(b * CT + t) * CG + g) * CF)[c];
            }
            float* d = &x_sh[r * XST + c * 4];
            d[0] = v.x; d[1] = v.y; d[2] = v.z; d[3] = v.w;
        }
    }
    __syncthreads();

    // ---- Register tile: 8 t's x 6 o's per thread ----
    float acc[8][6];
    #pragma unroll
    for (int i = 0; i < 8; i++)
        #pragma unroll
        for (int j = 0; j < 6; j++)
            acc[i][j] = 0.f;

    const int obase = tx * 6;

    #pragma unroll
    for (int k = 0; k < CK; k++) {
        const float* xp = &x_sh[(ty + k) * XST];          // + i*16*XST + f
        const float* wp = &w_sh[obase * WST + k];         // + j*WST + f*3
        #pragma unroll 2
        for (int f = 0; f < CF; f++) {
            float xr[8];
            #pragma unroll
            for (int i = 0; i < 8; i++)
                xr[i] = xp[i * 16 * XST + f];
            #pragma unroll
            for (int j = 0; j < 6; j++) {
                float wv = wp[j * WST + f * 3];
                #pragma unroll
                for (int i = 0; i < 8; i++)
                    acc[i][j] = fmaf(xr[i], wv, acc[i][j]);
            }
        }
    }

    // ---- Bias + writeback ----
    const float* bg = bias + g * CO + obase;
    float bv[6];
    #pragma unroll
    for (int j = 0; j < 6; j++) bv[j] = bg[j];

    #pragma unroll
    for (int i = 0; i < 8; i++) {
        int t = t0 + ty + i * 16;
        float* op = out + ((size_t)(b * CT + t) * CG + g) * CO + obase;
        #pragma unroll
        for (int j = 0; j < 6; j += 2) {
            float2 v2 = make_float2(acc[i][j] + bv[j], acc[i][j + 1] + bv[j + 1]);
            *reinterpret_cast<float2*>(op + j) = v2;
        }
    }
}

extern "C" void kernel_launch(void* const* d_in, const int* in_sizes, int n_in,
                              void* d_out, int out_size)
{
    const float* x    = (const float*)d_in[0];
    const float* w    = (const float*)d_in[1];
    const float* bias = (const float*)d_in[2];
    float* out        = (float*)d_out;

    cudaFuncSetAttribute(conv1d_group_kernel,
                         cudaFuncAttributeMaxDynamicSharedMemorySize, SMEM_BYTES);

    dim3 grid(CG, CT / TILE_T, CB);   // 129 x 4 x 4 = 2064 blocks
    conv1d_group_kernel<<<grid, 256, SMEM_BYTES>>>(x, w, bias, out);
}

// round 3
// speedup vs baseline: 3.0947x; 3.0947x over previous
#include <cuda_runtime.h>
#include <cuda_bf16.h>
#include <cstdint>

// Conv1dGroup as 129 bf16-split tcgen05 GEMMs (sm_103a), with FFMA fallback
// for non-'a' compilation passes.
// out[b,t,g,o] = sum_{f,k} x[b,t+k-1,g,f] * w[g,o,f,k] + bias[g,o]
// GEMM per g: D[M=2048 (b,t), N=96 (o)] = A[M, K=288 (k*96+f)] * B[N, K]^T
// bf16 2-way split: v = hi + lo; D = Ah*Bh + Al*Bh + Ah*Bl (fp32 TMEM accum).

#define CB 4
#define CT 512
#define CG 129
#define CF 96
#define CO 96
#define CK 3

#define KPAD 320                       // 5 atom-cols of 64 bf16
#define NATOM_B (CO / 8)               // 12 atoms per atom-col of B
#define ACOL_B (NATOM_B * 1024)        // 12288 bytes
#define B_G_BYTES (5 * ACOL_B)         // 61440 bytes per group per term

#define SWZ(x) ((x) ^ (((x) >> 3) & 0x70))

// idesc: F32 accum, BF16 a/b, N=96, M=128  (same encoding as 0x8080490 @N=32)
#define IDESC ((1u<<4) | (1u<<7) | (1u<<10) | ((CO/8)<<17) | ((128/16)<<24))

// SMEM map (bytes)
#define SM_BHI     0
#define SM_BLO     61440
#define SM_A       122880              // 2 x (Ahi 16384 + Alo 16384)
#define SM_BIAS    188416
#define SM_TMEMPTR 188800
#define SM_MBAR    188816
#define SMEM_TOTAL 189440

#if defined(__CUDA_ARCH_FEAT_SM103_ALL) || defined(__CUDA_ARCH_FEAT_SM100_ALL)
#define CONV_HAS_TCGEN05 1
#else
#define CONV_HAS_TCGEN05 0
#endif

__device__ __align__(16) unsigned char g_whi[CG * B_G_BYTES];
__device__ __align__(16) unsigned char g_wlo[CG * B_G_BYTES];

// ---------------- helpers ----------------

static __device__ __forceinline__ uint32_t smem_u32(const void* p) {
    uint32_t a;
    asm("{ .reg .u64 t; cvta.to.shared.u64 t, %1; cvt.u32.u64 %0, t; }" : "=r"(a) : "l"(p));
    return a;
}

static __device__ __forceinline__ uint32_t bf16x2_of(float lo, float hi) {
    uint32_t r;
    asm("cvt.rn.bf16x2.f32 %0, %1, %2;" : "=r"(r) : "f"(hi), "f"(lo));
    return r;
}

#define MBARRIER_INIT(addr, cnt) \
    asm volatile("mbarrier.init.shared.b64 [%0], %1;" :: "r"(addr), "r"(cnt) : "memory")
#define MBARRIER_INVAL(addr) \
    asm volatile("mbarrier.inval.shared.b64 [%0];" :: "r"(addr) : "memory")
#define MBARRIER_WAIT_PARITY(addr, parity) do {                                    \
    asm volatile(                                                                  \
        "{\n\t.reg .pred P;\n\t"                                                   \
        "WL_%=:\n\t"                                                               \
        "mbarrier.try_wait.parity.acquire.cta.shared::cta.b64 P, [%0], %1, 0x989680;\n\t" \
        "@P bra.uni WD_%=;\n\t"                                                    \
        "bra.uni WL_%=;\n\t"                                                       \
        "WD_%=:\n\t}"                                                              \
        :: "r"((uint32_t)(addr)), "r"((uint32_t)(parity)) : "memory");             \
} while (0)
#define FENCE_PROXY_ASYNC() asm volatile("fence.proxy.async.shared::cta;" ::: "memory")

#if CONV_HAS_TCGEN05

#define TCGEN05_ALLOC(smaddr, ncols) \
    asm volatile("tcgen05.alloc.cta_group::1.sync.aligned.shared::cta.b32 [%0], %1;" \
                 :: "r"((uint32_t)(smaddr)), "r"((uint32_t)(ncols)) : "memory")
#define TCGEN05_DEALLOC(tm, ncols) \
    asm volatile("tcgen05.dealloc.cta_group::1.sync.aligned.b32 %0, %1;" \
                 :: "r"(tm), "r"((uint32_t)(ncols)))
#define TCGEN05_COMMIT(mbar) \
    asm volatile("tcgen05.commit.cta_group::1.mbarrier::arrive::one.shared::cluster.b64 [%0];" \
                 :: "r"((uint32_t)(mbar)) : "memory")
#define TCGEN05_WAIT_LD() asm volatile("tcgen05.wait::ld.sync.aligned;" ::: "memory")
#define TCGEN05_FENCE_BEFORE() asm volatile("tcgen05.fence::before_thread_sync;" ::: "memory")
#define TCGEN05_FENCE_AFTER()  asm volatile("tcgen05.fence::after_thread_sync;" ::: "memory")

#define TCGEN05_LD_32X32B_X16(r, tmaddr) \
    asm volatile( \
        "tcgen05.ld.sync.aligned.32x32b.x16.b32 " \
        "{%0, %1, %2, %3, %4, %5, %6, %7, " \
        " %8, %9, %10, %11, %12, %13, %14, %15}, [%16];" \
        : "=r"((r)[0]),  "=r"((r)[1]),  "=r"((r)[2]),  "=r"((r)[3]), \
          "=r"((r)[4]),  "=r"((r)[5]),  "=r"((r)[6]),  "=r"((r)[7]), \
          "=r"((r)[8]),  "=r"((r)[9]),  "=r"((r)[10]), "=r"((r)[11]), \
          "=r"((r)[12]), "=r"((r)[13]), "=r"((r)[14]), "=r"((r)[15]) \
        : "r"(tmaddr))

static constexpr uint64_t SMEM_DESC_BASE_SW128 =
    (uint64_t(2) << 61) | (uint64_t(1) << 46) | (uint64_t(64) << 32) | (uint64_t(1) << 16);

static __device__ __forceinline__ uint64_t make_desc(uint32_t smaddr) {
    return SMEM_DESC_BASE_SW128 | ((uint64_t)(smaddr >> 4) & 0x3FFF);
}

static __device__ __forceinline__ void mma_f16_ss(uint32_t d, uint64_t a, uint64_t b,
                                                  uint32_t idesc, uint32_t en) {
    asm volatile(
        "{\n\t.reg .pred p;\n\t"
        "setp.ne.u32 p, %4, 0;\n\t"
        "tcgen05.mma.cta_group::1.kind::f16 [%0], %1, %2, %3, p;\n\t}"
        :: "r"(d), "l"(a), "l"(b), "r"(idesc), "r"(en) : "memory");
}

#endif // CONV_HAS_TCGEN05

// ---------------- pre-kernel: weights -> bf16 hi/lo in MMA SMEM layout ----------------

__global__ __launch_bounds__(256) void prep_w(const float* __restrict__ w) {
    int id = blockIdx.x * 256 + threadIdx.x;
    const int NTASK = CG * CO * (KPAD / 2);
    if (id >= NTASK) return;
    int K2 = id % (KPAD / 2);
    int o  = (id / (KPAD / 2)) % CO;
    int g  = id / ((KPAD / 2) * CO);
    int K  = K2 * 2;

    float2 v = make_float2(0.f, 0.f);
    if (K < CF * CK) {
        int k = K / CF;                      // K = k*96 + f, f even
        int f = K - CF * k;
        const float* p = w + (((size_t)(g * CO + o) * CF + f) * CK + k);
        v.x = p[0];
        v.y = p[CK];
    }
    uint32_t hi = bf16x2_of(v.x, v.y);
    float hx = __uint_as_float(hi << 16);
    float hy = __uint_as_float(hi & 0xFFFF0000u);
    uint32_t lo = bf16x2_of(v.x - hx, v.y - hy);

    uint32_t addr = (uint32_t)g * B_G_BYTES + (K >> 6) * ACOL_B + (o >> 3) * 1024
                  + SWZ(((o & 7) << 7) | ((K & 63) * 2));
    *(uint32_t*)(g_whi + addr) = hi;
    *(uint32_t*)(g_wlo + addr) = lo;
}

// ---------------- main tcgen05 kernel ----------------

__global__ __launch_bounds__(256, 1)
void conv_mma(const float* __restrict__ x, const float* __restrict__ bias,
              float* __restrict__ out)
{
#if CONV_HAS_TCGEN05
    extern __shared__ __align__(1024) unsigned char sm[];
    const uint32_t smb = smem_u32(sm);
    const int tid = threadIdx.x;
    const int g = blockIdx.x;
    const int wid = tid >> 5, lid = tid & 31;

    // Stage B (hi+lo) for this group: raw byte copy (already in MMA layout)
    {
        const uint4* shi = (const uint4*)(g_whi + (size_t)g * B_G_BYTES);
        const uint4* slo = (const uint4*)(g_wlo + (size_t)g * B_G_BYTES);
        uint4* dhi = (uint4*)(sm + SM_BHI);
        uint4* dlo = (uint4*)(sm + SM_BLO);
        #pragma unroll 5
        for (int i = tid; i < B_G_BYTES / 16; i += 256) { dhi[i] = shi[i]; dlo[i] = slo[i]; }
    }
    {
        float* bsm = (float*)(sm + SM_BIAS);
        if (tid < CO) bsm[tid] = bias[g * CO + tid];
    }
    if (tid == 0) {
        MBARRIER_INIT(smb + SM_MBAR + 0, 1);
        MBARRIER_INIT(smb + SM_MBAR + 8, 1);
        MBARRIER_INIT(smb + SM_MBAR + 16, 1);
        MBARRIER_INIT(smb + SM_MBAR + 24, 1);
    }
    if (wid == 0) TCGEN05_ALLOC(smb + SM_TMEMPTR, 256);
    __syncthreads();

    uint32_t tmem;
    asm volatile("ld.shared.b32 %0, [%1];" : "=r"(tmem) : "r"(smb + SM_TMEMPTR));

    int ph_c0 = 0, ph_c1 = 0, ph_d0 = 0, ph_d1 = 0;
    int cc = 0;

    const int j = tid & 31;             // K-pair column within chunk
    const int warp16 = (tid >> 5) * 16; // base t row for this warp

    for (int tile = 0; tile < 16; ++tile) {
        const int bb = tile >> 2;
        const int t0 = (tile & 3) << 7;
        const uint32_t dslot = tmem + (uint32_t)((tile & 1) * 128);

        for (int c = 0; c < 5; ++c) {
            const int s = cc & 1;
            if (cc >= 2) {
                if (s == 0) { MBARRIER_WAIT_PARITY(smb + SM_MBAR + 0, ph_c0); ph_c0 ^= 1; }
                else        { MBARRIER_WAIT_PARITY(smb + SM_MBAR + 8, ph_c1); ph_c1 ^= 1; }
            }
            // ---- stage A chunk c into buffer s (unfold + bf16 split) ----
            {
                const int K = c * 64 + j * 2;
                const bool kvalid = (K < CF * CK);
                const int k = K / CF;
                const int f = K - CF * k;
                const float* xp = x
                    + (((size_t)bb * CT + (size_t)(t0 - 1 + warp16 + k)) * CG + g) * CF + f;
                unsigned char* abh = sm + SM_A + s * 32768;
                unsigned char* abl = abh + 16384;
                #pragma unroll
                for (int st = 0; st < 16; ++st) {
                    const int t = warp16 + st;
                    const int gt = t0 - 1 + t + k;
                    float2 v = make_float2(0.f, 0.f);
                    if (kvalid && gt >= 0 && gt < CT) v = *(const float2*)xp;
                    uint32_t hi = bf16x2_of(v.x, v.y);
                    float hx = __uint_as_float(hi << 16);
                    float hy = __uint_as_float(hi & 0xFFFF0000u);
                    uint32_t lo = bf16x2_of(v.x - hx, v.y - hy);
                    const uint32_t off = ((uint32_t)(t >> 3) << 10)
                                       + SWZ(((t & 7) << 7) | (j << 2));
                    *(uint32_t*)(abh + off) = hi;
                    *(uint32_t*)(abl + off) = lo;
                    xp += (size_t)CG * CF;          // advance one t row
                }
            }
            __syncthreads();
            if (tid == 0) {
                FENCE_PROXY_ASYNC();
                TCGEN05_FENCE_AFTER();
                const uint64_t ah = make_desc(smb + SM_A + s * 32768);
                const uint64_t al = make_desc(smb + SM_A + s * 32768 + 16384);
                const uint64_t bh = make_desc(smb + SM_BHI + c * ACOL_B);
                const uint64_t bl = make_desc(smb + SM_BLO + c * ACOL_B);
                #pragma unroll
                for (int stp = 0; stp < 4; ++stp) {
                    uint32_t en0 = (c > 0 || stp > 0) ? 1u : 0u;
                    mma_f16_ss(dslot, ah + 2 * stp, bh + 2 * stp, IDESC, en0);
                    mma_f16_ss(dslot, al + 2 * stp, bh + 2 * stp, IDESC, 1u);
                    mma_f16_ss(dslot, ah + 2 * stp, bl + 2 * stp, IDESC, 1u);
                }
                if (s == 0) TCGEN05_COMMIT(smb + SM_MBAR + 0);
                else        TCGEN05_COMMIT(smb + SM_MBAR + 8);
                if (c == 4) {
                    if (tile & 1) TCGEN05_COMMIT(smb + SM_MBAR + 24);
                    else          TCGEN05_COMMIT(smb + SM_MBAR + 16);
                }
            }
            cc++;
        }

        // ---- epilogue for tile-1 (overlaps this tile's in-flight MMAs) ----
        if (tile >= 1) {
            const int et = tile - 1;
            const int es = et & 1;
            if (es == 0) { MBARRIER_WAIT_PARITY(smb + SM_MBAR + 16, ph_d0); ph_d0 ^= 1; }
            else         { MBARRIER_WAIT_PARITY(smb + SM_MBAR + 24, ph_d1); ph_d1 ^= 1; }
            TCGEN05_FENCE_AFTER();
            const int colbase = (tid >> 7) * 48;
            const int row = ((wid & 3) << 5) + lid;
            const int ebb = et >> 2, et0 = (et & 3) << 7;
            float* op = out + (((size_t)ebb * CT + et0 + row) * CG + g) * CO + colbase;
            const float* bsm = (const float*)(sm + SM_BIAS) + colbase;
            const uint32_t D = tmem + (uint32_t)(es * 128) + colbase;
            #pragma unroll
            for (int bch = 0; bch < 3; ++bch) {
                uint32_t r[16];
                TCGEN05_LD_32X32B_X16(r, D + bch * 16);
                TCGEN05_WAIT_LD();
                #pragma unroll
                for (int q = 0; q < 4; ++q) {
                    float4 v;
                    v.x = __uint_as_float(r[q * 4 + 0]) + bsm[bch * 16 + q * 4 + 0];
                    v.y = __uint_as_float(r[q * 4 + 1]) + bsm[bch * 16 + q * 4 + 1];
                    v.z = __uint_as_float(r[q * 4 + 2]) + bsm[bch * 16 + q * 4 + 2];
                    v.w = __uint_as_float(r[q * 4 + 3]) + bsm[bch * 16 + q * 4 + 3];
                    *(float4*)(op + bch * 16 + q * 4) = v;
                }
            }
            TCGEN05_FENCE_BEFORE();
        }
    }

    // ---- epilogue for last tile (15) ----
    {
        MBARRIER_WAIT_PARITY(smb + SM_MBAR + 24, ph_d1); ph_d1 ^= 1;
        TCGEN05_FENCE_AFTER();
        const int colbase = (tid >> 7) * 48;
        const int row = ((wid & 3) << 5) + lid;
        float* op = out + (((size_t)3 * CT + 384 + row) * CG + g) * CO + colbase;
        const float* bsm = (const float*)(sm + SM_BIAS) + colbase;
        const uint32_t D = tmem + 128 + colbase;
        #pragma unroll
        for (int bch = 0; bch < 3; ++bch) {
            uint32_t r[16];
            TCGEN05_LD_32X32B_X16(r, D + bch * 16);
            TCGEN05_WAIT_LD();
            #pragma unroll
            for (int q = 0; q < 4; ++q) {
                float4 v;
                v.x = __uint_as_float(r[q * 4 + 0]) + bsm[bch * 16 + q * 4 + 0];
                v.y = __uint_as_float(r[q * 4 + 1]) + bsm[bch * 16 + q * 4 + 1];
                v.z = __uint_as_float(r[q * 4 + 2]) + bsm[bch * 16 + q * 4 + 2];
                v.w = __uint_as_float(r[q * 4 + 3]) + bsm[bch * 16 + q * 4 + 3];
                *(float4*)(op + bch * 16 + q * 4) = v;
            }
        }
        TCGEN05_FENCE_BEFORE();
    }

    __syncthreads();
    if (tid == 0) {
        MBARRIER_INVAL(smb + SM_MBAR + 0);
        MBARRIER_INVAL(smb + SM_MBAR + 8);
        MBARRIER_INVAL(smb + SM_MBAR + 16);
        MBARRIER_INVAL(smb + SM_MBAR + 24);
    }
    __syncthreads();
    if (wid == 0) TCGEN05_DEALLOC(tmem, 256);
#endif // CONV_HAS_TCGEN05
}

// ---------------- FFMA fallback (known-good 438us kernel) ----------------

#define TILE_T 128
#define TT (TILE_T + 2)
#define XST (CF + 1)
#define FKc (CF * CK)
#define WST (FKc + 1)
#define FB_SMEM_FLOATS (CO * WST + TT * XST)
#define FB_SMEM_BYTES (FB_SMEM_FLOATS * 4)

__global__ __launch_bounds__(256, 1)
void conv_fallback(const float* __restrict__ x, const float* __restrict__ w,
                   const float* __restrict__ bias, float* __restrict__ out)
{
    extern __shared__ float sh[];
    float* w_sh = sh;
    float* x_sh = sh + CO * WST;

    const int g  = blockIdx.x;
    const int t0 = blockIdx.y * TILE_T;
    const int b  = blockIdx.z;
    const int tid = threadIdx.x;
    const int tx = tid & 15;
    const int ty = tid >> 4;

    {
        const float4* wg = reinterpret_cast<const float4*>(w + (size_t)g * CO * FKc);
        #pragma unroll 4
        for (int idx = tid; idx < CO * FKc / 4; idx += 256) {
            int o = idx / (FKc / 4);
            int c = idx - o * (FKc / 4);
            float4 v = wg[idx];
            float* d = &w_sh[o * WST + c * 4];
            d[0] = v.x; d[1] = v.y; d[2] = v.z; d[3] = v.w;
        }
    }
    {
        #pragma unroll 4
        for (int idx = tid; idx < TT * (CF / 4); idx += 256) {
            int r = idx / (CF / 4);
            int c = idx - r * (CF / 4);
            int t = t0 - 1 + r;
            float4 v = make_float4(0.f, 0.f, 0.f, 0.f);
            if (t >= 0 && t < CT)
                v = reinterpret_cast<const float4*>(
                        x + ((size_t)(b * CT + t) * CG + g) * CF)[c];
            float* d = &x_sh[r * XST + c * 4];
            d[0] = v.x; d[1] = v.y; d[2] = v.z; d[3] = v.w;
        }
    }
    __syncthreads();

    float acc[8][6];
    #pragma unroll
    for (int i = 0; i < 8; i++)
        #pragma unroll
        for (int jj = 0; jj < 6; jj++) acc[i][jj] = 0.f;

    const int obase = tx * 6;
    #pragma unroll
    for (int k = 0; k < CK; k++) {
        const float* xp = &x_sh[(ty + k) * XST];
        const float* wp = &w_sh[obase * WST + k];
        #pragma unroll 2
        for (int f = 0; f < CF; f++) {
            float xr[8];
            #pragma unroll
            for (int i = 0; i < 8; i++) xr[i] = xp[i * 16 * XST + f];
            #pragma unroll
            for (int jj = 0; jj < 6; jj++) {
                float wv = wp[jj * WST + f * 3];
                #pragma unroll
                for (int i = 0; i < 8; i++) acc[i][jj] = fmaf(xr[i], wv, acc[i][jj]);
            }
        }
    }

    const float* bg = bias + g * CO + obase;
    float bv[6];
    #pragma unroll
    for (int jj = 0; jj < 6; jj++) bv[jj] = bg[jj];

    #pragma unroll
    for (int i = 0; i < 8; i++) {
        int t = t0 + ty + i * 16;
        float* op = out + ((size_t)(b * CT + t) * CG + g) * CO + obase;
        #pragma unroll
        for (int jj = 0; jj < 6; jj += 2) {
            float2 v2 = make_float2(acc[i][jj] + bv[jj], acc[i][jj + 1] + bv[jj + 1]);
            *reinterpret_cast<float2*>(op + jj) = v2;
        }
    }
}

// ---------------- launch ----------------

extern "C" void kernel_launch(void* const* d_in, const int* in_sizes, int n_in,
                              void* d_out, int out_size)
{
    const float* x    = (const float*)d_in[0];
    const float* w    = (const float*)d_in[1];
    const float* bias = (const float*)d_in[2];
    float* out        = (float*)d_out;

    // Runtime dispatch: if the loaded cubin compiled the tcgen05 body
    // (sm_103a pass), conv_mma has many registers; the stub has few.
    cudaFuncAttributes attr{};
    cudaFuncGetAttributes(&attr, conv_mma);

    if (attr.numRegs >= 32) {
        const int ntask = CG * CO * (KPAD / 2);
        prep_w<<<(ntask + 255) / 256, 256>>>(w);
        cudaFuncSetAttribute(conv_mma,
                             cudaFuncAttributeMaxDynamicSharedMemorySize, SMEM_TOTAL);
        conv_mma<<<CG, 256, SMEM_TOTAL>>>(x, bias, out);
    } else {
        cudaFuncSetAttribute(conv_fallback,
                             cudaFuncAttributeMaxDynamicSharedMemorySize, FB_SMEM_BYTES);
        dim3 grid(CG, CT / TILE_T, CB);
        conv_fallback<<<grid, 256, FB_SMEM_BYTES>>>(x, w, bias, out);
    }
}